// round 14
// baseline (speedup 1.0000x reference)
#include <cuda_runtime.h>
#include <cuda_fp16.h>
#include <cstdint>

// ---------------------------------------------------------------------------
// Problem constants
// ---------------------------------------------------------------------------
namespace {
constexpr int Bsz   = 2;
constexpr int Tlen  = 2048;
constexpr int HID   = 1024;
constexpr int HEADS = 16;
constexpr int HDIM  = 64;
constexpr int BT    = Bsz * Tlen;   // 4096
constexpr int C3    = 3 * HID;      // 3072
}

// Q pre-scale folded into the QKV GEMM epilogue (fp32, before fp16 round):
// S = Q.K/sqrt(64) in log2-domain  =>  scale Q by log2(e)/8.
#define QSCALE 0.1803368801111244f

// Scratch (__device__ globals per allocation-free rule)
__device__ __half g_qkv[BT * C3];            // qkv projections (fp16; Q pre-scaled)
__device__ __half g_att[BT * HID];           // attention out (fp16)
__device__ __half g_xh[BT * HID];            // x rounded to fp16
__device__ __half g_wtqkv[C3 * HID];         // W_qkv^T [3072,1024] K-major fp16
__device__ __half g_wtproj[HID * HID];       // W_proj^T [1024,1024] fp16

// ---------------------------------------------------------------------------
// Helpers
// ---------------------------------------------------------------------------
__device__ __forceinline__ uint32_t smem_u32(const void* p) {
    uint32_t a;
    asm("{ .reg .u64 t; cvta.to.shared.u64 t, %1; cvt.u32.u64 %0, t; }"
        : "=r"(a) : "l"(p));
    return a;
}
__device__ __forceinline__ uint32_t f2h2(float lo, float hi) {
    uint32_t d;
    asm("cvt.rn.f16x2.f32 %0, %1, %2;" : "=r"(d) : "f"(hi), "f"(lo));
    return d;
}
__device__ __forceinline__ float ex2(float x) {   // 2^x, fast approx
    float y;
    asm("ex2.approx.ftz.f32 %0, %1;" : "=f"(y) : "f"(x));
    return y;
}
__device__ __forceinline__ void ldsm4(uint32_t& r0, uint32_t& r1,
                                      uint32_t& r2, uint32_t& r3, uint32_t a) {
    asm volatile("ldmatrix.sync.aligned.m8n8.x4.shared.b16 {%0,%1,%2,%3}, [%4];"
                 : "=r"(r0), "=r"(r1), "=r"(r2), "=r"(r3) : "r"(a));
}
__device__ __forceinline__ void ldsm4t(uint32_t& r0, uint32_t& r1,
                                       uint32_t& r2, uint32_t& r3, uint32_t a) {
    asm volatile(
        "ldmatrix.sync.aligned.m8n8.x4.trans.shared.b16 {%0,%1,%2,%3}, [%4];"
        : "=r"(r0), "=r"(r1), "=r"(r2), "=r"(r3) : "r"(a));
}
__device__ __forceinline__ void mma_f16(float* d, const uint32_t* a,
                                        const uint32_t* b) {
    asm volatile(
        "mma.sync.aligned.m16n8k16.row.col.f32.f16.f16.f32 "
        "{%0,%1,%2,%3}, {%4,%5,%6,%7}, {%8,%9}, {%0,%1,%2,%3};"
        : "+f"(d[0]), "+f"(d[1]), "+f"(d[2]), "+f"(d[3])
        : "r"(a[0]), "r"(a[1]), "r"(a[2]), "r"(a[3]), "r"(b[0]), "r"(b[1]));
}
__device__ __forceinline__ void cpasync16(uint32_t dst, const void* src) {
    asm volatile("cp.async.cg.shared.global [%0], [%1], 16;"
                 :: "r"(dst), "l"(src));
}

// Shared swizzled layout: 128B rows = 8 segs of 16B; conflict-free 8-row cycle.
#define G_OFF(row, seg) ((row) * 128 + ((((seg) ^ ((row) & 7))) * 16))

// ---------------------------------------------------------------------------
// FP16 mma.sync GEMM (verified):  C = A @ Bt^T + bias.
// 128x128 tile, BK=64, 8 warps (warp 64x32, m16n8k16), 3-stage cp.async
// pipeline, one __syncthreads per K-iteration, 2 CTAs/SM.
// Columns < scale_ncols get *ascale in fp32 before output (Q pre-scale).
// ---------------------------------------------------------------------------
constexpr int G_OPER  = 128 * 128;               // 16 KB
constexpr int G_STAGE = 2 * G_OPER;
constexpr int G_SMEM  = 3 * G_STAGE;             // 96 KB

__global__ __launch_bounds__(256, 2) void gemm_f16mma(
    const __half* __restrict__ A, const __half* __restrict__ Bt,
    const float* __restrict__ bias, void* __restrict__ Cout,
    int M, int N, int K, int out_half, int scale_ncols, float ascale)
{
    extern __shared__ __align__(128) char gsm[];
    const uint32_t s0 = smem_u32(gsm);

    const int tid = threadIdx.x, lane = tid & 31, wid = tid >> 5;
    const int bm = blockIdx.y * 128, bn = blockIdx.x * 128;
    const int warp_m = (wid & 1) * 64;
    const int warp_n = (wid >> 1) * 32;

    uint32_t ld_off[4];
    const __half *srcA[4], *srcB[4];
    #pragma unroll
    for (int i = 0; i < 4; i++) {
        int idx = i * 256 + tid;
        int row = idx >> 3, seg = idx & 7;
        ld_off[i] = G_OFF(row, seg);
        srcA[i] = A + (size_t)(bm + row) * K + seg * 8;
        srcB[i] = Bt + (size_t)(bn + row) * K + seg * 8;
    }
    auto issue = [&](int chunk, int stage) {
        const uint32_t ab = s0 + stage * G_STAGE;
        const uint32_t bb = ab + G_OPER;
        const int koff = chunk * 64;
        #pragma unroll
        for (int i = 0; i < 4; i++) {
            cpasync16(ab + ld_off[i], srcA[i] + koff);
            cpasync16(bb + ld_off[i], srcB[i] + koff);
        }
        asm volatile("cp.async.commit_group;");
    };

    uint32_t a_rowoff[4]; int a_sw[4];
    #pragma unroll
    for (int mt = 0; mt < 4; mt++) {
        int row = warp_m + mt * 16 + (lane & 7) + ((lane >> 3) & 1) * 8;
        a_rowoff[mt] = row * 128;
        a_sw[mt] = row & 7;
    }
    const int a_segbase = (lane >> 4);
    uint32_t b_rowoff[2]; int b_sw[2];
    #pragma unroll
    for (int np = 0; np < 2; np++) {
        int row = warp_n + np * 16 + ((lane >> 4) & 1) * 8 + (lane & 7);
        b_rowoff[np] = row * 128;
        b_sw[np] = row & 7;
    }
    const int b_segbase = ((lane >> 3) & 1);

    float acc[4][4][4];
    #pragma unroll
    for (int mt = 0; mt < 4; mt++)
        #pragma unroll
        for (int nt = 0; nt < 4; nt++)
            #pragma unroll
            for (int r = 0; r < 4; r++) acc[mt][nt][r] = 0.f;

    const int NIT = K >> 6;

    issue(0, 0);
    issue(1, 1);

    for (int c = 0; c < NIT; c++) {
        if (c < NIT - 1) {
            asm volatile("cp.async.wait_group 1;");
        } else {
            asm volatile("cp.async.wait_group 0;");
        }
        __syncthreads();
        if (c + 2 < NIT) issue(c + 2, (c + 2) % 3);

        const uint32_t ab = s0 + (c % 3) * G_STAGE;
        const uint32_t bb = ab + G_OPER;
        #pragma unroll
        for (int ks = 0; ks < 4; ks++) {
            uint32_t af[4][4], bf[2][4];
            #pragma unroll
            for (int mt = 0; mt < 4; mt++) {
                int seg = (2 * ks + a_segbase) ^ a_sw[mt];
                ldsm4(af[mt][0], af[mt][1], af[mt][2], af[mt][3],
                      ab + a_rowoff[mt] + seg * 16);
            }
            #pragma unroll
            for (int np = 0; np < 2; np++) {
                int seg = (2 * ks + b_segbase) ^ b_sw[np];
                ldsm4(bf[np][0], bf[np][1], bf[np][2], bf[np][3],
                      bb + b_rowoff[np] + seg * 16);
            }
            #pragma unroll
            for (int mt = 0; mt < 4; mt++)
                #pragma unroll
                for (int nt = 0; nt < 4; nt++)
                    mma_f16(acc[mt][nt], af[mt], bf[nt >> 1] + (nt & 1) * 2);
        }
    }

    const int er = lane >> 2, ec = (lane & 3) * 2;
    #pragma unroll
    for (int mt = 0; mt < 4; mt++) {
        const int row0 = bm + warp_m + mt * 16 + er;
        #pragma unroll
        for (int nt = 0; nt < 4; nt++) {
            const int col = bn + warp_n + nt * 8 + ec;
            const float sc = (col < scale_ncols) ? ascale : 1.f;
            const float b0 = bias[col], b1 = bias[col + 1];
            float c0 = (acc[mt][nt][0] + b0) * sc, c1 = (acc[mt][nt][1] + b1) * sc;
            float c2 = (acc[mt][nt][2] + b0) * sc, c3 = (acc[mt][nt][3] + b1) * sc;
            if (out_half) {
                __half* C = (__half*)Cout;
                *(uint32_t*)(C + (size_t)row0 * N + col)       = f2h2(c0, c1);
                *(uint32_t*)(C + (size_t)(row0 + 8) * N + col) = f2h2(c2, c3);
            } else {
                float* C = (float*)Cout;
                *(float2*)(C + (size_t)row0 * N + col)       = make_float2(c0, c1);
                *(float2*)(C + (size_t)(row0 + 8) * N + col) = make_float2(c2, c3);
            }
        }
    }
}

// ---------------------------------------------------------------------------
// Tensor-core causal flash attention: fp16 mma, fp32 softmax (log2-domain).
// FA2 register identity (P stays in registers); deferred l-reduction:
// per-thread partial row-sums accumulate through the loop, single quad
// shfl-reduce in the epilogue (cr is quad-uniform so the recurrence
// distributes over partials).
// ---------------------------------------------------------------------------
constexpr int FA_SMEM = 16384 + 2 * 8192 + 2 * 8192;   // 48KB

__global__ __launch_bounds__(256) void flash_mma(
    const __half* __restrict__ qkv, __half* __restrict__ out)
{
    extern __shared__ char fsm[];
    const uint32_t sQ = smem_u32(fsm);         // 16KB
    const uint32_t sK = sQ + 16384;            // 2 x 8KB
    const uint32_t sV = sQ + 32768;            // 2 x 8KB
    const int tid = threadIdx.x, lane = tid & 31, w = tid >> 5;
    const int qb = gridDim.x - 1 - blockIdx.x;
    const int bh = blockIdx.y;
    const int b = bh >> 4, h = bh & 15;

    const __half* qbase = qkv + (size_t)b * Tlen * C3 + h * HDIM;
    const __half* kbase = qbase + HID;
    const __half* vbase = qbase + 2 * HID;

    auto loadKV = [&](int kb, int s) {
        const uint32_t so = s * 8192;
        #pragma unroll
        for (int i = 0; i < 2; i++) {
            int idx = i * 256 + tid;
            int row = idx >> 3, seg = idx & 7;
            uint32_t off = G_OFF(row, seg);
            const size_t g = (size_t)(kb * 64 + row) * C3 + seg * 8;
            cpasync16(sK + so + off, kbase + g);
            cpasync16(sV + so + off, vbase + g);
        }
    };

    #pragma unroll
    for (int i = 0; i < 4; i++) {
        int idx = i * 256 + tid;
        int row = idx >> 3, seg = idx & 7;
        cpasync16(sQ + G_OFF(row, seg),
                  qbase + (size_t)(qb * 128 + row) * C3 + seg * 8);
    }
    loadKV(0, 0);
    asm volatile("cp.async.commit_group;");
    asm volatile("cp.async.wait_group 0;");
    __syncthreads();

    const int frow = w * 16 + (lane & 7) + ((lane >> 3) & 1) * 8;
    const uint32_t frow_b = frow * 128;
    const int frow_s = frow & 7;
    const int fseg_hi = lane >> 4;

    uint32_t qf[4][4];
    #pragma unroll
    for (int ks = 0; ks < 4; ks++)
        ldsm4(qf[ks][0], qf[ks][1], qf[ks][2], qf[ks][3],
              sQ + frow_b + (((2 * ks + fseg_hi) ^ frow_s) * 16));

    uint32_t browb[4]; int brows[4];
    #pragma unroll
    for (int np = 0; np < 4; np++) {
        int row = np * 16 + ((lane >> 4) & 1) * 8 + (lane & 7);
        browb[np] = row * 128;
        brows[np] = row & 7;
    }
    const int bseg_lo = (lane >> 3) & 1;

    const int vrow_base = ((lane >> 3) & 1) * 8 + (lane & 7);
    const int vseg_base = (lane >> 4) & 1;

    float O[8][4];
    #pragma unroll
    for (int nt = 0; nt < 8; nt++)
        #pragma unroll
        for (int r = 0; r < 4; r++) O[nt][r] = 0.f;
    float m0 = -1e30f, m1 = -1e30f, l0 = 0.f, l1 = 0.f;  // l: per-thread partials
    bool first = true;

    const int rw = qb * 128 + w * 16;
    const int nkb = 2 * qb + 2;
    const int c0off = 2 * (lane & 3);
    const int r0g = rw + (lane >> 2);
    const int r1g = r0g + 8;

    for (int kb = 0; kb < nkb; kb++) {
        const int s = kb & 1;
        if (kb + 1 < nkb) {
            loadKV(kb + 1, 1 - s);
            asm volatile("cp.async.commit_group;");
            asm volatile("cp.async.wait_group 1;");
        } else {
            asm volatile("cp.async.wait_group 0;");
        }
        __syncthreads();

        if (kb * 64 <= rw + 15) {
            const uint32_t Kb = sK + s * 8192, Vb = sV + s * 8192;
            float S[8][4];
            #pragma unroll
            for (int nt = 0; nt < 8; nt++)
                #pragma unroll
                for (int r = 0; r < 4; r++) S[nt][r] = 0.f;

            // S = Q' @ K^T   (Q' already scaled by log2e/8)
            #pragma unroll
            for (int ks = 0; ks < 4; ks++) {
                uint32_t kf[4][4];
                #pragma unroll
                for (int np = 0; np < 4; np++) {
                    int seg = (2 * ks + bseg_lo) ^ brows[np];
                    ldsm4(kf[np][0], kf[np][1], kf[np][2], kf[np][3],
                          Kb + browb[np] + seg * 16);
                }
                #pragma unroll
                for (int nt = 0; nt < 8; nt++)
                    mma_f16(S[nt], qf[ks], kf[nt >> 1] + (nt & 1) * 2);
            }

            // causal mask (diagonal tiles only)
            if (kb * 64 + 63 > rw) {
                #pragma unroll
                for (int nt = 0; nt < 8; nt++) {
                    int c = kb * 64 + nt * 8 + c0off;
                    if (c     > r0g) S[nt][0] = -1e30f;
                    if (c + 1 > r0g) S[nt][1] = -1e30f;
                    if (c     > r1g) S[nt][2] = -1e30f;
                    if (c + 1 > r1g) S[nt][3] = -1e30f;
                }
            }

            // online softmax in log2-domain (max reduce only; l deferred)
            float mx0 = -1e30f, mx1 = -1e30f;
            #pragma unroll
            for (int nt = 0; nt < 8; nt++) {
                mx0 = fmaxf(mx0, fmaxf(S[nt][0], S[nt][1]));
                mx1 = fmaxf(mx1, fmaxf(S[nt][2], S[nt][3]));
            }
            mx0 = fmaxf(mx0, __shfl_xor_sync(0xffffffffu, mx0, 1));
            mx0 = fmaxf(mx0, __shfl_xor_sync(0xffffffffu, mx0, 2));
            mx1 = fmaxf(mx1, __shfl_xor_sync(0xffffffffu, mx1, 1));
            mx1 = fmaxf(mx1, __shfl_xor_sync(0xffffffffu, mx1, 2));
            const float mn0 = fmaxf(m0, mx0), mn1 = fmaxf(m1, mx1);
            const float cr0 = ex2(m0 - mn0), cr1 = ex2(m1 - mn1);
            float sum0 = 0.f, sum1 = 0.f;
            #pragma unroll
            for (int nt = 0; nt < 8; nt++) {
                S[nt][0] = ex2(S[nt][0] - mn0);
                S[nt][1] = ex2(S[nt][1] - mn0);
                S[nt][2] = ex2(S[nt][2] - mn1);
                S[nt][3] = ex2(S[nt][3] - mn1);
                sum0 += S[nt][0] + S[nt][1];
                sum1 += S[nt][2] + S[nt][3];
            }
            m0 = mn0; m1 = mn1;
            if (first) {
                l0 = sum0; l1 = sum1;
                first = false;
            } else {
                l0 = l0 * cr0 + sum0;
                l1 = l1 * cr1 + sum1;
                #pragma unroll
                for (int nt = 0; nt < 8; nt++) {
                    O[nt][0] *= cr0; O[nt][1] *= cr0;
                    O[nt][2] *= cr1; O[nt][3] *= cr1;
                }
            }

            // O += P @ V — P straight from S registers (FA2 identity)
            #pragma unroll
            for (int ks = 0; ks < 4; ks++) {
                uint32_t pf[4];
                pf[0] = f2h2(S[2 * ks][0],     S[2 * ks][1]);
                pf[1] = f2h2(S[2 * ks][2],     S[2 * ks][3]);
                pf[2] = f2h2(S[2 * ks + 1][0], S[2 * ks + 1][1]);
                pf[3] = f2h2(S[2 * ks + 1][2], S[2 * ks + 1][3]);
                const int vrow = 16 * ks + vrow_base;
                const uint32_t vrb = Vb + vrow * 128;
                const int vsw = vrow & 7;
                uint32_t vf[4][4];
                #pragma unroll
                for (int np = 0; np < 4; np++) {
                    int seg = (2 * np + vseg_base) ^ vsw;
                    ldsm4t(vf[np][0], vf[np][1], vf[np][2], vf[np][3],
                           vrb + seg * 16);
                }
                #pragma unroll
                for (int nt = 0; nt < 8; nt++)
                    mma_f16(O[nt], pf, vf[nt >> 1] + (nt & 1) * 2);
            }
        }
        __syncthreads();
    }

    // epilogue: single quad-reduction of the deferred l partials
    l0 += __shfl_xor_sync(0xffffffffu, l0, 1);
    l0 += __shfl_xor_sync(0xffffffffu, l0, 2);
    l1 += __shfl_xor_sync(0xffffffffu, l1, 1);
    l1 += __shfl_xor_sync(0xffffffffu, l1, 2);
    const float i0 = 1.f / l0, i1 = 1.f / l1;
    #pragma unroll
    for (int nt = 0; nt < 8; nt++) {
        const int col = h * HDIM + nt * 8 + c0off;
        *(uint32_t*)(out + (size_t)(b * Tlen + r0g) * HID + col) =
            f2h2(O[nt][0] * i0, O[nt][1] * i0);
        *(uint32_t*)(out + (size_t)(b * Tlen + r1g) * HID + col) =
            f2h2(O[nt][2] * i1, O[nt][3] * i1);
    }
}

// ---------------------------------------------------------------------------
// Fused pre-pass (verified R9): x->fp16 round + both weight transposes.
// ---------------------------------------------------------------------------
__global__ __launch_bounds__(256) void prepass(
    const float* __restrict__ x,
    const float* __restrict__ Wqkv, const float* __restrict__ Wproj,
    __half* __restrict__ xh,
    __half* __restrict__ wtqkv, __half* __restrict__ wtproj)
{
    const int bx = blockIdx.x, tid = threadIdx.x;
    if (bx < 4096) {
        int i = bx * 256 + tid;
        float4 v = ((const float4*)x)[i];
        uint2 o;
        o.x = f2h2(v.x, v.y);
        o.y = f2h2(v.z, v.w);
        ((uint2*)xh)[i] = o;
        return;
    }
    __shared__ float tile[32][33];
    const float* in;
    __half* out;
    int K, N, n0, k0;
    if (bx < 7168) {
        int b2 = bx - 4096;
        in = Wqkv; out = wtqkv; K = HID; N = C3;
        n0 = (b2 % 96) * 32; k0 = (b2 / 96) * 32;
    } else {
        int b2 = bx - 7168;
        in = Wproj; out = wtproj; K = HID; N = HID;
        n0 = (b2 % 32) * 32; k0 = (b2 / 32) * 32;
    }
    const int tx = tid & 31, ty = tid >> 5;
    #pragma unroll
    for (int i = 0; i < 32; i += 8)
        tile[ty + i][tx] = in[(size_t)(k0 + ty + i) * N + n0 + tx];
    __syncthreads();
    #pragma unroll
    for (int i = 0; i < 32; i += 8)
        out[(size_t)(n0 + ty + i) * K + k0 + tx] = __float2half(tile[tx][ty + i]);
}

// ---------------------------------------------------------------------------
// Launch
// ---------------------------------------------------------------------------
extern "C" void kernel_launch(void* const* d_in, const int* in_sizes, int n_in,
                              void* d_out, int out_size)
{
    const float* x     = (const float*)d_in[0];
    const float* Wqkv  = (const float*)d_in[1];
    const float* bqkv  = (const float*)d_in[2];
    const float* Wproj = (const float*)d_in[3];
    const float* bproj = (const float*)d_in[4];
    float* out = (float*)d_out;

    __half *qkv_p, *att_p, *xh_p, *wtqkv_p, *wtproj_p;
    cudaGetSymbolAddress((void**)&qkv_p,    g_qkv);
    cudaGetSymbolAddress((void**)&att_p,    g_att);
    cudaGetSymbolAddress((void**)&xh_p,     g_xh);
    cudaGetSymbolAddress((void**)&wtqkv_p,  g_wtqkv);
    cudaGetSymbolAddress((void**)&wtproj_p, g_wtproj);

    cudaFuncSetAttribute(gemm_f16mma,
                         cudaFuncAttributeMaxDynamicSharedMemorySize, G_SMEM);
    cudaFuncSetAttribute(flash_mma,
                         cudaFuncAttributeMaxDynamicSharedMemorySize, FA_SMEM);

    // 0) fused pre-pass
    prepass<<<8192, 256>>>(x, Wqkv, Wproj, xh_p, wtqkv_p, wtproj_p);
    // 1) qkv = xh @ Wqkv^T + b -> fp16; Q columns (<1024) pre-scaled by log2e/8
    gemm_f16mma<<<dim3(C3 / 128, BT / 128), 256, G_SMEM>>>(
        xh_p, wtqkv_p, bqkv, qkv_p, BT, C3, HID, 1, HID, QSCALE);
    // 2) tensor-core causal flash attention -> fp16 (register-resident P)
    flash_mma<<<dim3(Tlen / 128, Bsz * HEADS), 256, FA_SMEM>>>(qkv_p, att_p);
    // 3) out = att @ Wproj^T + b -> f32
    gemm_f16mma<<<dim3(HID / 128, BT / 128), 256, G_SMEM>>>(
        att_p, wtproj_p, bproj, out, BT, HID, HID, 0, 0, 1.f);
}

// round 16
// speedup vs baseline: 1.1006x; 1.1006x over previous
#include <cuda_runtime.h>
#include <cuda_fp16.h>
#include <cstdint>

// ---------------------------------------------------------------------------
// Problem constants
// ---------------------------------------------------------------------------
namespace {
constexpr int Bsz   = 2;
constexpr int Tlen  = 2048;
constexpr int HID   = 1024;
constexpr int HEADS = 16;
constexpr int HDIM  = 64;
constexpr int BT    = Bsz * Tlen;   // 4096
constexpr int C3    = 3 * HID;      // 3072
}

// Q pre-scale folded into the QKV GEMM epilogue (fp32, before fp16 round):
// S = Q.K/sqrt(64) in log2-domain  =>  scale Q by log2(e)/8.
#define QSCALE 0.1803368801111244f

// Scratch (__device__ globals per allocation-free rule)
__device__ __half g_qkv[BT * C3];            // qkv projections (fp16; Q pre-scaled)
__device__ __half g_att[BT * HID];           // attention out (fp16)
__device__ __half g_xh[BT * HID];            // x rounded to fp16
__device__ __half g_wtqkv[C3 * HID];         // W_qkv^T [3072,1024] K-major fp16
__device__ __half g_wtproj[HID * HID];       // W_proj^T [1024,1024] fp16

// ---------------------------------------------------------------------------
// Helpers
// ---------------------------------------------------------------------------
__device__ __forceinline__ uint32_t smem_u32(const void* p) {
    uint32_t a;
    asm("{ .reg .u64 t; cvta.to.shared.u64 t, %1; cvt.u32.u64 %0, t; }"
        : "=r"(a) : "l"(p));
    return a;
}
__device__ __forceinline__ uint32_t f2h2(float lo, float hi) {
    uint32_t d;
    asm("cvt.rn.f16x2.f32 %0, %1, %2;" : "=r"(d) : "f"(hi), "f"(lo));
    return d;
}
__device__ __forceinline__ float ex2(float x) {   // 2^x, fast approx
    float y;
    asm("ex2.approx.ftz.f32 %0, %1;" : "=f"(y) : "f"(x));
    return y;
}
__device__ __forceinline__ void ldsm4(uint32_t& r0, uint32_t& r1,
                                      uint32_t& r2, uint32_t& r3, uint32_t a) {
    asm volatile("ldmatrix.sync.aligned.m8n8.x4.shared.b16 {%0,%1,%2,%3}, [%4];"
                 : "=r"(r0), "=r"(r1), "=r"(r2), "=r"(r3) : "r"(a));
}
__device__ __forceinline__ void ldsm4t(uint32_t& r0, uint32_t& r1,
                                       uint32_t& r2, uint32_t& r3, uint32_t a) {
    asm volatile(
        "ldmatrix.sync.aligned.m8n8.x4.trans.shared.b16 {%0,%1,%2,%3}, [%4];"
        : "=r"(r0), "=r"(r1), "=r"(r2), "=r"(r3) : "r"(a));
}
__device__ __forceinline__ void mma_f16(float* d, const uint32_t* a,
                                        const uint32_t* b) {
    asm volatile(
        "mma.sync.aligned.m16n8k16.row.col.f32.f16.f16.f32 "
        "{%0,%1,%2,%3}, {%4,%5,%6,%7}, {%8,%9}, {%0,%1,%2,%3};"
        : "+f"(d[0]), "+f"(d[1]), "+f"(d[2]), "+f"(d[3])
        : "r"(a[0]), "r"(a[1]), "r"(a[2]), "r"(a[3]), "r"(b[0]), "r"(b[1]));
}
__device__ __forceinline__ void cpasync16(uint32_t dst, const void* src) {
    asm volatile("cp.async.cg.shared.global [%0], [%1], 16;"
                 :: "r"(dst), "l"(src));
}

// Shared swizzled layout: 128B rows = 8 segs of 16B; conflict-free 8-row cycle.
#define G_OFF(row, seg) ((row) * 128 + ((((seg) ^ ((row) & 7))) * 16))

// ---------------------------------------------------------------------------
// FP16 mma.sync GEMM (verified):  C = A @ Bt^T + bias.
// 128x128 tile, BK=64, 8 warps (warp 64x32, m16n8k16), 3-stage cp.async
// pipeline, one __syncthreads per K-iteration, 2 CTAs/SM.
// Columns < scale_ncols get *ascale in fp32 before output (Q pre-scale).
// ---------------------------------------------------------------------------
constexpr int G_OPER  = 128 * 128;               // 16 KB
constexpr int G_STAGE = 2 * G_OPER;
constexpr int G_SMEM  = 3 * G_STAGE;             // 96 KB

__global__ __launch_bounds__(256, 2) void gemm_f16mma(
    const __half* __restrict__ A, const __half* __restrict__ Bt,
    const float* __restrict__ bias, void* __restrict__ Cout,
    int M, int N, int K, int out_half, int scale_ncols, float ascale)
{
    extern __shared__ __align__(128) char gsm[];
    const uint32_t s0 = smem_u32(gsm);

    const int tid = threadIdx.x, lane = tid & 31, wid = tid >> 5;
    const int bm = blockIdx.y * 128, bn = blockIdx.x * 128;
    const int warp_m = (wid & 1) * 64;
    const int warp_n = (wid >> 1) * 32;

    uint32_t ld_off[4];
    const __half *srcA[4], *srcB[4];
    #pragma unroll
    for (int i = 0; i < 4; i++) {
        int idx = i * 256 + tid;
        int row = idx >> 3, seg = idx & 7;
        ld_off[i] = G_OFF(row, seg);
        srcA[i] = A + (size_t)(bm + row) * K + seg * 8;
        srcB[i] = Bt + (size_t)(bn + row) * K + seg * 8;
    }
    auto issue = [&](int chunk, int stage) {
        const uint32_t ab = s0 + stage * G_STAGE;
        const uint32_t bb = ab + G_OPER;
        const int koff = chunk * 64;
        #pragma unroll
        for (int i = 0; i < 4; i++) {
            cpasync16(ab + ld_off[i], srcA[i] + koff);
            cpasync16(bb + ld_off[i], srcB[i] + koff);
        }
        asm volatile("cp.async.commit_group;");
    };

    uint32_t a_rowoff[4]; int a_sw[4];
    #pragma unroll
    for (int mt = 0; mt < 4; mt++) {
        int row = warp_m + mt * 16 + (lane & 7) + ((lane >> 3) & 1) * 8;
        a_rowoff[mt] = row * 128;
        a_sw[mt] = row & 7;
    }
    const int a_segbase = (lane >> 4);
    uint32_t b_rowoff[2]; int b_sw[2];
    #pragma unroll
    for (int np = 0; np < 2; np++) {
        int row = warp_n + np * 16 + ((lane >> 4) & 1) * 8 + (lane & 7);
        b_rowoff[np] = row * 128;
        b_sw[np] = row & 7;
    }
    const int b_segbase = ((lane >> 3) & 1);

    float acc[4][4][4];
    #pragma unroll
    for (int mt = 0; mt < 4; mt++)
        #pragma unroll
        for (int nt = 0; nt < 4; nt++)
            #pragma unroll
            for (int r = 0; r < 4; r++) acc[mt][nt][r] = 0.f;

    const int NIT = K >> 6;

    issue(0, 0);
    issue(1, 1);

    for (int c = 0; c < NIT; c++) {
        if (c < NIT - 1) {
            asm volatile("cp.async.wait_group 1;");
        } else {
            asm volatile("cp.async.wait_group 0;");
        }
        __syncthreads();
        if (c + 2 < NIT) issue(c + 2, (c + 2) % 3);

        const uint32_t ab = s0 + (c % 3) * G_STAGE;
        const uint32_t bb = ab + G_OPER;
        #pragma unroll
        for (int ks = 0; ks < 4; ks++) {
            uint32_t af[4][4], bf[2][4];
            #pragma unroll
            for (int mt = 0; mt < 4; mt++) {
                int seg = (2 * ks + a_segbase) ^ a_sw[mt];
                ldsm4(af[mt][0], af[mt][1], af[mt][2], af[mt][3],
                      ab + a_rowoff[mt] + seg * 16);
            }
            #pragma unroll
            for (int np = 0; np < 2; np++) {
                int seg = (2 * ks + b_segbase) ^ b_sw[np];
                ldsm4(bf[np][0], bf[np][1], bf[np][2], bf[np][3],
                      bb + b_rowoff[np] + seg * 16);
            }
            #pragma unroll
            for (int mt = 0; mt < 4; mt++)
                #pragma unroll
                for (int nt = 0; nt < 4; nt++)
                    mma_f16(acc[mt][nt], af[mt], bf[nt >> 1] + (nt & 1) * 2);
        }
    }

    const int er = lane >> 2, ec = (lane & 3) * 2;
    #pragma unroll
    for (int mt = 0; mt < 4; mt++) {
        const int row0 = bm + warp_m + mt * 16 + er;
        #pragma unroll
        for (int nt = 0; nt < 4; nt++) {
            const int col = bn + warp_n + nt * 8 + ec;
            const float sc = (col < scale_ncols) ? ascale : 1.f;
            const float b0 = bias[col], b1 = bias[col + 1];
            float c0 = (acc[mt][nt][0] + b0) * sc, c1 = (acc[mt][nt][1] + b1) * sc;
            float c2 = (acc[mt][nt][2] + b0) * sc, c3 = (acc[mt][nt][3] + b1) * sc;
            if (out_half) {
                __half* C = (__half*)Cout;
                *(uint32_t*)(C + (size_t)row0 * N + col)       = f2h2(c0, c1);
                *(uint32_t*)(C + (size_t)(row0 + 8) * N + col) = f2h2(c2, c3);
            } else {
                float* C = (float*)Cout;
                *(float2*)(C + (size_t)row0 * N + col)       = make_float2(c0, c1);
                *(float2*)(C + (size_t)(row0 + 8) * N + col) = make_float2(c2, c3);
            }
        }
    }
}

// ---------------------------------------------------------------------------
// Tensor-core causal flash attention: 64 q-rows per CTA, 4 warps (128 thr).
// Finer barrier domains: ~4 CTAs/SM so barrier stalls in one CTA are covered
// by the other three. fp16 mma, fp32 log2-domain softmax, FA2 register-P,
// deferred-l quad reduction, V^T via ldmatrix.trans.
// smem: Q 8KB + 2 x (K 8KB + V 8KB) = 40KB.
// ---------------------------------------------------------------------------
constexpr int FA_SMEM = 8192 + 2 * 8192 + 2 * 8192;   // 40KB

__global__ __launch_bounds__(128) void flash_mma(
    const __half* __restrict__ qkv, __half* __restrict__ out)
{
    extern __shared__ char fsm[];
    const uint32_t sQ = smem_u32(fsm);         // 8KB
    const uint32_t sK = sQ + 8192;             // 2 x 8KB
    const uint32_t sV = sQ + 24576;            // 2 x 8KB
    const int tid = threadIdx.x, lane = tid & 31, w = tid >> 5;  // w: 0..3
    const int qb = gridDim.x - 1 - blockIdx.x; // heavy blocks first
    const int bh = blockIdx.y;
    const int b = bh >> 4, h = bh & 15;

    const __half* qbase = qkv + (size_t)b * Tlen * C3 + h * HDIM;
    const __half* kbase = qbase + HID;
    const __half* vbase = qbase + 2 * HID;

    auto loadKV = [&](int kb, int s) {
        const uint32_t so = s * 8192;
        #pragma unroll
        for (int i = 0; i < 4; i++) {          // 64 rows x 8 segs = 512
            int idx = i * 128 + tid;
            int row = idx >> 3, seg = idx & 7;
            uint32_t off = G_OFF(row, seg);
            const size_t g = (size_t)(kb * 64 + row) * C3 + seg * 8;
            cpasync16(sK + so + off, kbase + g);
            cpasync16(sV + so + off, vbase + g);
        }
    };

    #pragma unroll
    for (int i = 0; i < 4; i++) {              // Q: 64 rows x 8 segs
        int idx = i * 128 + tid;
        int row = idx >> 3, seg = idx & 7;
        cpasync16(sQ + G_OFF(row, seg),
                  qbase + (size_t)(qb * 64 + row) * C3 + seg * 8);
    }
    loadKV(0, 0);
    asm volatile("cp.async.commit_group;");
    asm volatile("cp.async.wait_group 0;");
    __syncthreads();

    // A-frag geometry (Q; rows warp-private within the 64-row tile)
    const int frow = w * 16 + (lane & 7) + ((lane >> 3) & 1) * 8;
    const uint32_t frow_b = frow * 128;
    const int frow_s = frow & 7;
    const int fseg_hi = lane >> 4;

    uint32_t qf[4][4];
    #pragma unroll
    for (int ks = 0; ks < 4; ks++)
        ldsm4(qf[ks][0], qf[ks][1], qf[ks][2], qf[ks][3],
              sQ + frow_b + (((2 * ks + fseg_hi) ^ frow_s) * 16));

    uint32_t browb[4]; int brows[4];
    #pragma unroll
    for (int np = 0; np < 4; np++) {
        int row = np * 16 + ((lane >> 4) & 1) * 8 + (lane & 7);
        browb[np] = row * 128;
        brows[np] = row & 7;
    }
    const int bseg_lo = (lane >> 3) & 1;

    const int vrow_base = ((lane >> 3) & 1) * 8 + (lane & 7);
    const int vseg_base = (lane >> 4) & 1;

    float O[8][4];
    #pragma unroll
    for (int nt = 0; nt < 8; nt++)
        #pragma unroll
        for (int r = 0; r < 4; r++) O[nt][r] = 0.f;
    float m0 = -1e30f, m1 = -1e30f, l0 = 0.f, l1 = 0.f;
    bool first = true;

    const int rw = qb * 64 + w * 16;
    const int nkb = qb + 1;                    // key tiles 0..qb
    const int c0off = 2 * (lane & 3);
    const int r0g = rw + (lane >> 2);
    const int r1g = r0g + 8;

    for (int kb = 0; kb < nkb; kb++) {
        const int s = kb & 1;
        if (kb + 1 < nkb) {
            loadKV(kb + 1, 1 - s);
            asm volatile("cp.async.commit_group;");
            asm volatile("cp.async.wait_group 1;");
        } else {
            asm volatile("cp.async.wait_group 0;");
        }
        __syncthreads();

        const uint32_t Kb = sK + s * 8192, Vb = sV + s * 8192;
        float S[8][4];
        #pragma unroll
        for (int nt = 0; nt < 8; nt++)
            #pragma unroll
            for (int r = 0; r < 4; r++) S[nt][r] = 0.f;

        // S = Q' @ K^T   (Q' already scaled by log2e/8)
        #pragma unroll
        for (int ks = 0; ks < 4; ks++) {
            uint32_t kf[4][4];
            #pragma unroll
            for (int np = 0; np < 4; np++) {
                int seg = (2 * ks + bseg_lo) ^ brows[np];
                ldsm4(kf[np][0], kf[np][1], kf[np][2], kf[np][3],
                      Kb + browb[np] + seg * 16);
            }
            #pragma unroll
            for (int nt = 0; nt < 8; nt++)
                mma_f16(S[nt], qf[ks], kf[nt >> 1] + (nt & 1) * 2);
        }

        // causal mask (diagonal tile kb == qb only)
        if (kb == nkb - 1) {
            #pragma unroll
            for (int nt = 0; nt < 8; nt++) {
                int c = kb * 64 + nt * 8 + c0off;
                if (c     > r0g) S[nt][0] = -1e30f;
                if (c + 1 > r0g) S[nt][1] = -1e30f;
                if (c     > r1g) S[nt][2] = -1e30f;
                if (c + 1 > r1g) S[nt][3] = -1e30f;
            }
        }

        // online softmax in log2-domain (max reduce only; l deferred)
        float mx0 = -1e30f, mx1 = -1e30f;
        #pragma unroll
        for (int nt = 0; nt < 8; nt++) {
            mx0 = fmaxf(mx0, fmaxf(S[nt][0], S[nt][1]));
            mx1 = fmaxf(mx1, fmaxf(S[nt][2], S[nt][3]));
        }
        mx0 = fmaxf(mx0, __shfl_xor_sync(0xffffffffu, mx0, 1));
        mx0 = fmaxf(mx0, __shfl_xor_sync(0xffffffffu, mx0, 2));
        mx1 = fmaxf(mx1, __shfl_xor_sync(0xffffffffu, mx1, 1));
        mx1 = fmaxf(mx1, __shfl_xor_sync(0xffffffffu, mx1, 2));
        const float mn0 = fmaxf(m0, mx0), mn1 = fmaxf(m1, mx1);
        const float cr0 = ex2(m0 - mn0), cr1 = ex2(m1 - mn1);
        float sum0 = 0.f, sum1 = 0.f;
        #pragma unroll
        for (int nt = 0; nt < 8; nt++) {
            S[nt][0] = ex2(S[nt][0] - mn0);
            S[nt][1] = ex2(S[nt][1] - mn0);
            S[nt][2] = ex2(S[nt][2] - mn1);
            S[nt][3] = ex2(S[nt][3] - mn1);
            sum0 += S[nt][0] + S[nt][1];
            sum1 += S[nt][2] + S[nt][3];
        }
        m0 = mn0; m1 = mn1;
        if (first) {
            l0 = sum0; l1 = sum1;
            first = false;
        } else {
            l0 = l0 * cr0 + sum0;
            l1 = l1 * cr1 + sum1;
            #pragma unroll
            for (int nt = 0; nt < 8; nt++) {
                O[nt][0] *= cr0; O[nt][1] *= cr0;
                O[nt][2] *= cr1; O[nt][3] *= cr1;
            }
        }

        // O += P @ V — P straight from S registers (FA2 identity)
        #pragma unroll
        for (int ks = 0; ks < 4; ks++) {
            uint32_t pf[4];
            pf[0] = f2h2(S[2 * ks][0],     S[2 * ks][1]);
            pf[1] = f2h2(S[2 * ks][2],     S[2 * ks][3]);
            pf[2] = f2h2(S[2 * ks + 1][0], S[2 * ks + 1][1]);
            pf[3] = f2h2(S[2 * ks + 1][2], S[2 * ks + 1][3]);
            const int vrow = 16 * ks + vrow_base;
            const uint32_t vrb = Vb + vrow * 128;
            const int vsw = vrow & 7;
            uint32_t vf[4][4];
            #pragma unroll
            for (int np = 0; np < 4; np++) {
                int seg = (2 * np + vseg_base) ^ vsw;
                ldsm4t(vf[np][0], vf[np][1], vf[np][2], vf[np][3],
                       vrb + seg * 16);
            }
            #pragma unroll
            for (int nt = 0; nt < 8; nt++)
                mma_f16(O[nt], pf, vf[nt >> 1] + (nt & 1) * 2);
        }
        __syncthreads();
    }

    // epilogue: single quad-reduction of the deferred l partials
    l0 += __shfl_xor_sync(0xffffffffu, l0, 1);
    l0 += __shfl_xor_sync(0xffffffffu, l0, 2);
    l1 += __shfl_xor_sync(0xffffffffu, l1, 1);
    l1 += __shfl_xor_sync(0xffffffffu, l1, 2);
    const float i0 = 1.f / l0, i1 = 1.f / l1;
    #pragma unroll
    for (int nt = 0; nt < 8; nt++) {
        const int col = h * HDIM + nt * 8 + c0off;
        *(uint32_t*)(out + (size_t)(b * Tlen + r0g) * HID + col) =
            f2h2(O[nt][0] * i0, O[nt][1] * i0);
        *(uint32_t*)(out + (size_t)(b * Tlen + r1g) * HID + col) =
            f2h2(O[nt][2] * i1, O[nt][3] * i1);
    }
}

// ---------------------------------------------------------------------------
// Fused pre-pass (verified R9): x->fp16 round + both weight transposes.
// ---------------------------------------------------------------------------
__global__ __launch_bounds__(256) void prepass(
    const float* __restrict__ x,
    const float* __restrict__ Wqkv, const float* __restrict__ Wproj,
    __half* __restrict__ xh,
    __half* __restrict__ wtqkv, __half* __restrict__ wtproj)
{
    const int bx = blockIdx.x, tid = threadIdx.x;
    if (bx < 4096) {
        int i = bx * 256 + tid;
        float4 v = ((const float4*)x)[i];
        uint2 o;
        o.x = f2h2(v.x, v.y);
        o.y = f2h2(v.z, v.w);
        ((uint2*)xh)[i] = o;
        return;
    }
    __shared__ float tile[32][33];
    const float* in;
    __half* out;
    int K, N, n0, k0;
    if (bx < 7168) {
        int b2 = bx - 4096;
        in = Wqkv; out = wtqkv; K = HID; N = C3;
        n0 = (b2 % 96) * 32; k0 = (b2 / 96) * 32;
    } else {
        int b2 = bx - 7168;
        in = Wproj; out = wtproj; K = HID; N = HID;
        n0 = (b2 % 32) * 32; k0 = (b2 / 32) * 32;
    }
    const int tx = tid & 31, ty = tid >> 5;
    #pragma unroll
    for (int i = 0; i < 32; i += 8)
        tile[ty + i][tx] = in[(size_t)(k0 + ty + i) * N + n0 + tx];
    __syncthreads();
    #pragma unroll
    for (int i = 0; i < 32; i += 8)
        out[(size_t)(n0 + ty + i) * K + k0 + tx] = __float2half(tile[tx][ty + i]);
}

// ---------------------------------------------------------------------------
// Launch
// ---------------------------------------------------------------------------
extern "C" void kernel_launch(void* const* d_in, const int* in_sizes, int n_in,
                              void* d_out, int out_size)
{
    const float* x     = (const float*)d_in[0];
    const float* Wqkv  = (const float*)d_in[1];
    const float* bqkv  = (const float*)d_in[2];
    const float* Wproj = (const float*)d_in[3];
    const float* bproj = (const float*)d_in[4];
    float* out = (float*)d_out;

    __half *qkv_p, *att_p, *xh_p, *wtqkv_p, *wtproj_p;
    cudaGetSymbolAddress((void**)&qkv_p,    g_qkv);
    cudaGetSymbolAddress((void**)&att_p,    g_att);
    cudaGetSymbolAddress((void**)&xh_p,     g_xh);
    cudaGetSymbolAddress((void**)&wtqkv_p,  g_wtqkv);
    cudaGetSymbolAddress((void**)&wtproj_p, g_wtproj);

    cudaFuncSetAttribute(gemm_f16mma,
                         cudaFuncAttributeMaxDynamicSharedMemorySize, G_SMEM);
    cudaFuncSetAttribute(flash_mma,
                         cudaFuncAttributeMaxDynamicSharedMemorySize, FA_SMEM);

    // 0) fused pre-pass
    prepass<<<8192, 256>>>(x, Wqkv, Wproj, xh_p, wtqkv_p, wtproj_p);
    // 1) qkv = xh @ Wqkv^T + b -> fp16; Q columns (<1024) pre-scaled by log2e/8
    gemm_f16mma<<<dim3(C3 / 128, BT / 128), 256, G_SMEM>>>(
        xh_p, wtqkv_p, bqkv, qkv_p, BT, C3, HID, 1, HID, QSCALE);
    // 2) causal flash attention, 64-row CTAs -> fp16
    flash_mma<<<dim3(Tlen / 64, Bsz * HEADS), 128, FA_SMEM>>>(qkv_p, att_p);
    // 3) out = att @ Wproj^T + b -> f32
    gemm_f16mma<<<dim3(HID / 128, BT / 128), 256, G_SMEM>>>(
        att_p, wtproj_p, bproj, out, BT, HID, HID, 0, 0, 1.f);
}